// round 15
// baseline (speedup 1.0000x reference)
#include <cuda_runtime.h>
#include <cuda_fp16.h>
#include <math.h>
#include <cstdint>

#define NB 4
#define NS 2048
#define ND 1024
#define NH 16
#define NKV 4
#define NHD 64
#define MTOT (NB * NS)   // 8192

// ---------------- scratch (static device globals; no allocation) -------------
__device__ __half g_xh[(size_t)MTOT * ND];
__device__ __half g_qh[(size_t)MTOT * ND];
__device__ __half g_kh[(size_t)MTOT * 256];
__device__ __half g_vh[(size_t)MTOT * 256];
__device__ __half g_oh[(size_t)MTOT * ND];
__device__ __half g_wqh[(size_t)ND * ND];
__device__ __half g_wkh[(size_t)ND * 256];
__device__ __half g_wvh[(size_t)ND * 256];
__device__ __half g_woh[(size_t)ND * ND];

// ---------------- helpers -----------------------------------------------------
__device__ __forceinline__ float ex2(float x) {
    float y;
    asm("ex2.approx.f32 %0, %1;" : "=f"(y) : "f"(x));
    return y;
}
__device__ __forceinline__ uint32_t h2ex2(uint32_t x) {
    uint32_t y;
    asm("ex2.approx.f16x2 %0, %1;" : "=r"(y) : "r"(x));
    return y;
}
__device__ __forceinline__ uint32_t smem_u32(const void* p) {
    uint32_t a;
    asm("{ .reg .u64 t; cvta.to.shared.u64 t, %1; cvt.u32.u64 %0, t; }" : "=r"(a) : "l"(p));
    return a;
}
__device__ __forceinline__ uint32_t packh2(float lo, float hi) {
    __half2 h = __floats2half2_rn(lo, hi);
    return *reinterpret_cast<uint32_t*>(&h);
}
__device__ __forceinline__ void ldmx4(uint32_t* r, uint32_t addr) {
    asm volatile("ldmatrix.sync.aligned.m8n8.x4.shared.b16 {%0,%1,%2,%3}, [%4];"
                 : "=r"(r[0]), "=r"(r[1]), "=r"(r[2]), "=r"(r[3]) : "r"(addr));
}
__device__ __forceinline__ void ldmx4t(uint32_t* r, uint32_t addr) {
    asm volatile("ldmatrix.sync.aligned.m8n8.x4.trans.shared.b16 {%0,%1,%2,%3}, [%4];"
                 : "=r"(r[0]), "=r"(r[1]), "=r"(r[2]), "=r"(r[3]) : "r"(addr));
}
__device__ __forceinline__ void cpa16(uint32_t dst, const void* src) {
    asm volatile("cp.async.ca.shared.global [%0], [%1], 16;" :: "r"(dst), "l"(src));
}
__device__ __forceinline__ void cpa_commit() {
    asm volatile("cp.async.commit_group;" ::: "memory");
}
__device__ __forceinline__ void cpa_wait0() {
    asm volatile("cp.async.wait_group 0;" ::: "memory");
}
__device__ __forceinline__ void cpa_wait1() {
    asm volatile("cp.async.wait_group 1;" ::: "memory");
}
__device__ __forceinline__ void mma16(float* c, const uint32_t* a, uint32_t b0, uint32_t b1) {
    asm volatile(
        "mma.sync.aligned.m16n8k16.row.col.f32.f16.f16.f32 "
        "{%0,%1,%2,%3}, {%4,%5,%6,%7}, {%8,%9}, {%0,%1,%2,%3};"
        : "+f"(c[0]), "+f"(c[1]), "+f"(c[2]), "+f"(c[3])
        : "r"(a[0]), "r"(a[1]), "r"(a[2]), "r"(a[3]), "r"(b0), "r"(b1));
}

// ---------------- merged fp32->fp16 convert kernel ---------------------------
#define RN0 (MTOT * ND / 4)
#define RN1 (RN0 + ND * ND / 4)
#define RN2 (RN1 + ND * 256 / 4)
#define RN3 (RN2 + ND * 256 / 4)
#define RN4 (RN3 + ND * ND / 4)

__global__ __launch_bounds__(256) void cvt_all(
    const float* __restrict__ x,  __half* __restrict__ xh,
    const float* __restrict__ wq, __half* __restrict__ wqh,
    const float* __restrict__ wk, __half* __restrict__ wkh,
    const float* __restrict__ wv, __half* __restrict__ wvh,
    const float* __restrict__ wo, __half* __restrict__ woh) {
    int i = blockIdx.x * 256 + threadIdx.x;
    const float* s; __half* d; int j;
    if (i < RN0)      { s = x;  d = xh;  j = i; }
    else if (i < RN1) { s = wq; d = wqh; j = i - RN0; }
    else if (i < RN2) { s = wk; d = wkh; j = i - RN1; }
    else if (i < RN3) { s = wv; d = wvh; j = i - RN2; }
    else if (i < RN4) { s = wo; d = woh; j = i - RN3; }
    else return;
    float4 v = ((const float4*)s)[j];
    ((uint2*)d)[j] = make_uint2(packh2(v.x, v.y), packh2(v.z, v.w));
}

// ---------------- fp16 GEMM: tile 128x64x32, warp 64x32, 3-stage -------------
// 128 thr (4 warps 2x2). Small tiles kill wave-quantization tails; 4 blk/SM.
#define APH 20                        // A row pitch in words (32 fp16 + pad)
#define WPH 36                        // W row pitch in words (64 fp16 + pad)
#define ABUFW (128 * APH)             // 2560 words
#define WBUFW (32 * WPH)              // 1152 words
#define GSW (3 * (ABUFW + WBUFW))     // 11136 words = 44544 B

template <bool H16OUT>
__device__ __forceinline__ void tgemm_body(const __half* __restrict__ A,
                                           const __half* __restrict__ W,
                                           void* __restrict__ Cv,
                                           int N, int K, int bn, uint32_t* sm) {
    const int tid = threadIdx.x, wid = tid >> 5, lane = tid & 31;
    const int g = lane >> 2, tg = lane & 3;
    const int bm = blockIdx.y;
    const int wm = wid >> 1, wn = wid & 1;
    const int rowsel = lane & 15, colsel = lane >> 4;

    const uint32_t smb = smem_u32(sm);
    const uint32_t ws0 = 3 * ABUFW;

    const __half* Ap = A + (size_t)(bm * 128 + tid) * K;    // one A row per thread
    const int wrow = tid >> 3, wseg = tid & 7;              // W: 16 rows x 8 segs
    const __half* Wp = W + (size_t)wrow * N + bn * 64 + wseg * 8;

    const int nk = K / 32;

    auto load_tile = [&](int kt, int buf) {
        const uint32_t ab = smb + (uint32_t)(buf * ABUFW) * 4;
        const uint32_t wb = smb + (uint32_t)(ws0 + buf * WBUFW) * 4;
        const __half* ap = Ap + kt * 32;
#pragma unroll
        for (int s = 0; s < 4; s++)
            cpa16(ab + (uint32_t)(tid * APH + s * 4) * 4, ap + s * 8);
        const __half* wp = Wp + (size_t)kt * 32 * N;
#pragma unroll
        for (int r = 0; r < 2; r++)
            cpa16(wb + (uint32_t)((wrow + r * 16) * WPH + wseg * 4) * 4,
                  wp + (size_t)r * 16 * N);
        cpa_commit();
    };

    float acc[4][4][4];
#pragma unroll
    for (int i = 0; i < 4; i++)
#pragma unroll
        for (int j = 0; j < 4; j++)
#pragma unroll
            for (int r = 0; r < 4; r++) acc[i][j][r] = 0.f;

    load_tile(0, 0);
    load_tile(1, 1);

    int cur = 0;
    for (int kt = 0; kt < nk; kt++) {
        if (kt + 1 < nk) cpa_wait1(); else cpa_wait0();
        __syncthreads();
        int pre = cur + 2; if (pre >= 3) pre -= 3;
        if (kt + 2 < nk) load_tile(kt + 2, pre);

        const uint32_t ab = smb + (uint32_t)(cur * ABUFW) * 4;
        const uint32_t wb = smb + (uint32_t)(ws0 + cur * WBUFW) * 4;
#pragma unroll
        for (int ks = 0; ks < 2; ks++) {
            uint32_t a[4][4];
#pragma unroll
            for (int mt = 0; mt < 4; mt++)
                ldmx4(a[mt], ab + (uint32_t)((wm * 64 + mt * 16 + rowsel) * APH +
                                             ks * 8 + colsel * 4) * 4);
#pragma unroll
            for (int np = 0; np < 2; np++) {
                uint32_t r4[4];
                ldmx4t(r4, wb + (uint32_t)((ks * 16 + rowsel) * WPH +
                                           wn * 16 + np * 8 + colsel * 4) * 4);
#pragma unroll
                for (int mt = 0; mt < 4; mt++) {
                    mma16(acc[mt][2 * np],     a[mt], r4[0], r4[1]);
                    mma16(acc[mt][2 * np + 1], a[mt], r4[2], r4[3]);
                }
            }
        }
        if (++cur == 3) cur = 0;
    }

#pragma unroll
    for (int mt = 0; mt < 4; mt++)
#pragma unroll
        for (int nt = 0; nt < 4; nt++) {
            int row = bm * 128 + wm * 64 + mt * 16 + g;
            int col = bn * 64 + wn * 32 + nt * 8 + 2 * tg;
            if (H16OUT) {
                uint32_t* C = (uint32_t*)Cv;
                C[((size_t)row * N + col) >> 1] = packh2(acc[mt][nt][0], acc[mt][nt][1]);
                C[((size_t)(row + 8) * N + col) >> 1] = packh2(acc[mt][nt][2], acc[mt][nt][3]);
            } else {
                float* C = (float*)Cv;
                *(float2*)(C + (size_t)row * N + col) =
                    make_float2(acc[mt][nt][0], acc[mt][nt][1]);
                *(float2*)(C + (size_t)(row + 8) * N + col) =
                    make_float2(acc[mt][nt][2], acc[mt][nt][3]);
            }
        }
}

// merged QKV projection: grid (24, 64). 0-15 -> Q, 16-19 -> K, 20-23 -> V.
__global__ void __launch_bounds__(128, 4) tgemm_qkv(const __half* __restrict__ A,
                                                    const __half* __restrict__ wq,
                                                    const __half* __restrict__ wk,
                                                    const __half* __restrict__ wv,
                                                    __half* __restrict__ q,
                                                    __half* __restrict__ k,
                                                    __half* __restrict__ v) {
    extern __shared__ uint32_t smg[];
    const int bx = blockIdx.x;
    const __half* W; __half* C; int N, bn;
    if (bx < 16)      { W = wq; C = q; N = ND;  bn = bx; }
    else if (bx < 20) { W = wk; C = k; N = 256; bn = bx - 16; }
    else              { W = wv; C = v; N = 256; bn = bx - 20; }
    tgemm_body<true>(A, W, C, N, ND, bn, smg);
}

__global__ void __launch_bounds__(128, 4) tgemm_wo(const __half* __restrict__ A,
                                                   const __half* __restrict__ W,
                                                   float* __restrict__ C) {
    extern __shared__ uint32_t smg[];
    tgemm_body<false>(A, W, C, ND, ND, blockIdx.x, smg);
}

// ---------------- Flash attention, fp16 mma, static-max + ALiBi skip ---------
// e = s*sc2 + slope2*(j-(S-1)) is row-independent (softmax shift-invariance).
// Chunks with slope2*(S-1-j) > 24 are numerically irrelevant -> skip.
// exp via ex2.f16x2; row sums in fp32 via H2F unpack.
#define HP 36
#define SM_Q 0
#define KBUF (64 * HP)
#define SM_K (128 * HP)
#define SM_V (SM_K + 2 * KBUF)
#define SM_TOT (SM_V + 2 * KBUF)        // 13824 words = 55296 B

__global__ void __launch_bounds__(128, 2) attn_mma() {
    extern __shared__ uint32_t sm4[];
    const uint32_t smb = smem_u32(sm4);

    const int qb = blockIdx.x, b = blockIdx.z;
    const int h = (NH - 1) - blockIdx.y;    // heavy heads first
    const int kvh = h >> 2;
    const int tid = threadIdx.x, w = tid >> 5, lane = tid & 31;
    const int g = lane >> 2, tg = lane & 3;
    const int rowsel = lane & 15, colsel = lane >> 4;

    const float LOG2E = 1.4426950408889634f;
    const float sc2 = 0.125f * LOG2E;
    const float slope2 = ex2(-0.5f * (float)(h + 1)) * LOG2E;

    const int lr = tid >> 3;
    const int lseg = tid & 7;

    const int NCH = NS / 64;
    int nneed = (int)ceilf(24.f / (64.f * slope2));
    if (nneed > NCH) nneed = NCH;
    const int kt0 = NCH - nneed;

    const __half* kbase = g_kh + (size_t)(b * NS) * 256 + kvh * NHD;
    const __half* vbase = g_vh + (size_t)(b * NS) * 256 + kvh * NHD;

    auto issue_kv = [&](int kt, int buf) {
        const __half* kp = kbase + (size_t)kt * 64 * 256;
        const __half* vp = vbase + (size_t)kt * 64 * 256;
        const uint32_t kd = smb + (uint32_t)(SM_K + buf * KBUF) * 4;
        const uint32_t vd = smb + (uint32_t)(SM_V + buf * KBUF) * 4;
#pragma unroll
        for (int rep = 0; rep < 4; rep++) {
            int r = rep * 16 + lr;
            cpa16(kd + (uint32_t)(r * HP + lseg * 4) * 4, kp + (size_t)r * 256 + lseg * 8);
            cpa16(vd + (uint32_t)(r * HP + lseg * 4) * 4, vp + (size_t)r * 256 + lseg * 8);
        }
        cpa_commit();
    };

    issue_kv(kt0, 0);
    {
        const __half* qbase = g_qh + (size_t)(b * NS + qb * 128) * ND + h * NHD;
#pragma unroll
        for (int rep = 0; rep < 8; rep++) {
            int r = rep * 16 + lr;
            cpa16(smb + (uint32_t)(SM_Q + r * HP + lseg * 4) * 4,
                  qbase + (size_t)r * ND + lseg * 8);
        }
        cpa_commit();
    }
    cpa_wait0();
    __syncthreads();

    uint32_t qf[4][2][4];
#pragma unroll
    for (int ks = 0; ks < 4; ks++)
#pragma unroll
        for (int mt = 0; mt < 2; mt++)
            ldmx4(qf[ks][mt], smb + (uint32_t)(SM_Q +
                    (w * 32 + mt * 16 + rowsel) * HP + ks * 8 + colsel * 4) * 4);

    float l[4], O[2][8][4];
#pragma unroll
    for (int i = 0; i < 4; i++) l[i] = 0.f;
#pragma unroll
    for (int mt = 0; mt < 2; mt++)
#pragma unroll
        for (int nt = 0; nt < 8; nt++)
#pragma unroll
            for (int r = 0; r < 4; r++) O[mt][nt][r] = 0.f;

    for (int kt = kt0; kt < NCH; kt++) {
        const int kb = (kt - kt0) & 1;
        if (kt + 1 < NCH) issue_kv(kt + 1, kb ^ 1);

        const uint32_t kcur = smb + (uint32_t)(SM_K + kb * KBUF) * 4;
        const uint32_t vcur = smb + (uint32_t)(SM_V + kb * KBUF) * 4;

        // S = Q K^T
        float S[2][8][4];
#pragma unroll
        for (int mt = 0; mt < 2; mt++)
#pragma unroll
            for (int nt = 0; nt < 8; nt++)
#pragma unroll
                for (int r = 0; r < 4; r++) S[mt][nt][r] = 0.f;

#pragma unroll
        for (int ks = 0; ks < 4; ks++) {
#pragma unroll
            for (int np = 0; np < 4; np++) {
                uint32_t r4[4];
                ldmx4(r4, kcur + (uint32_t)((np * 16 + rowsel) * HP +
                                            ks * 8 + colsel * 4) * 4);
                mma16(S[0][2 * np],     qf[ks][0], r4[0], r4[2]);
                mma16(S[0][2 * np + 1], qf[ks][0], r4[1], r4[3]);
                mma16(S[1][2 * np],     qf[ks][1], r4[0], r4[2]);
                mma16(S[1][2 * np + 1], qf[ks][1], r4[1], r4[3]);
            }
        }

        // static-max softmax: e fp32, pack pairs, ex2.f16x2 -> P fragments
        const float base = slope2 * (float)(kt * 64 + 2 * tg - (NS - 1));
        uint32_t ph[2][4][4];
#pragma unroll
        for (int mt = 0; mt < 2; mt++) {
#pragma unroll
            for (int nt = 0; nt < 8; nt++) {
                const float b0 = fmaf((float)(8 * nt), slope2, base);
                const float b1 = b0 + slope2;
                S[mt][nt][0] = fmaf(S[mt][nt][0], sc2, b0);
                S[mt][nt][1] = fmaf(S[mt][nt][1], sc2, b1);
                S[mt][nt][2] = fmaf(S[mt][nt][2], sc2, b0);
                S[mt][nt][3] = fmaf(S[mt][nt][3], sc2, b1);
            }
#pragma unroll
            for (int ks = 0; ks < 4; ks++) {
                ph[mt][ks][0] = h2ex2(packh2(S[mt][2 * ks][0], S[mt][2 * ks][1]));
                ph[mt][ks][1] = h2ex2(packh2(S[mt][2 * ks][2], S[mt][2 * ks][3]));
                ph[mt][ks][2] = h2ex2(packh2(S[mt][2 * ks + 1][0], S[mt][2 * ks + 1][1]));
                ph[mt][ks][3] = h2ex2(packh2(S[mt][2 * ks + 1][2], S[mt][2 * ks + 1][3]));
            }
            float rs0 = 0.f, rs1 = 0.f;
#pragma unroll
            for (int ks = 0; ks < 4; ks++) {
                float2 a0 = __half22float2(*(__half2*)&ph[mt][ks][0]);
                float2 a2 = __half22float2(*(__half2*)&ph[mt][ks][2]);
                rs0 += (a0.x + a0.y) + (a2.x + a2.y);
                float2 a1 = __half22float2(*(__half2*)&ph[mt][ks][1]);
                float2 a3 = __half22float2(*(__half2*)&ph[mt][ks][3]);
                rs1 += (a1.x + a1.y) + (a3.x + a3.y);
            }
            rs0 += __shfl_xor_sync(0xffffffffu, rs0, 1);
            rs0 += __shfl_xor_sync(0xffffffffu, rs0, 2);
            rs1 += __shfl_xor_sync(0xffffffffu, rs1, 1);
            rs1 += __shfl_xor_sync(0xffffffffu, rs1, 2);
            l[2 * mt] += rs0;
            l[2 * mt + 1] += rs1;
        }

        // O += P @ V
#pragma unroll
        for (int ks = 0; ks < 4; ks++) {
#pragma unroll
            for (int np = 0; np < 4; np++) {
                uint32_t r4[4];
                ldmx4t(r4, vcur + (uint32_t)((ks * 16 + rowsel) * HP +
                                             np * 8 + colsel * 4) * 4);
                mma16(O[0][2 * np],     ph[0][ks], r4[0], r4[1]);
                mma16(O[0][2 * np + 1], ph[0][ks], r4[2], r4[3]);
                mma16(O[1][2 * np],     ph[1][ks], r4[0], r4[1]);
                mma16(O[1][2 * np + 1], ph[1][ks], r4[2], r4[3]);
            }
        }

        if (kt + 1 < NCH) {
            cpa_wait0();
            __syncthreads();
        }
    }

    // epilogue: normalize, pack fp16, store
#pragma unroll
    for (int mt = 0; mt < 2; mt++) {
        float inv0 = 1.f / l[2 * mt], inv1 = 1.f / l[2 * mt + 1];
        int rL = b * NS + qb * 128 + w * 32 + mt * 16 + g;
        uint32_t* ob = (uint32_t*)g_oh;
#pragma unroll
        for (int nt = 0; nt < 8; nt++) {
            int col = h * NHD + nt * 8 + 2 * tg;
            ob[((size_t)rL * ND + col) >> 1] =
                packh2(O[mt][nt][0] * inv0, O[mt][nt][1] * inv0);
            ob[((size_t)(rL + 8) * ND + col) >> 1] =
                packh2(O[mt][nt][2] * inv1, O[mt][nt][3] * inv1);
        }
    }
}

// ---------------- launch ------------------------------------------------------
extern "C" void kernel_launch(void* const* d_in, const int* in_sizes, int n_in,
                              void* d_out, int out_size) {
    const float* x  = (const float*)d_in[0];
    const float* Wq = (const float*)d_in[1];
    const float* Wk = (const float*)d_in[2];
    const float* Wv = (const float*)d_in[3];
    const float* Wo = (const float*)d_in[4];
    float* out = (float*)d_out;

    __half *xh, *qh, *kh, *vh, *oh, *wqh, *wkh, *wvh, *woh;
    cudaGetSymbolAddress((void**)&xh, g_xh);
    cudaGetSymbolAddress((void**)&qh, g_qh);
    cudaGetSymbolAddress((void**)&kh, g_kh);
    cudaGetSymbolAddress((void**)&vh, g_vh);
    cudaGetSymbolAddress((void**)&oh, g_oh);
    cudaGetSymbolAddress((void**)&wqh, g_wqh);
    cudaGetSymbolAddress((void**)&wkh, g_wkh);
    cudaGetSymbolAddress((void**)&wvh, g_wvh);
    cudaGetSymbolAddress((void**)&woh, g_woh);

    const int gsmem = GSW * sizeof(uint32_t);          // 44544 B
    const int smem_attn = SM_TOT * sizeof(uint32_t);   // 55296 B
    cudaFuncSetAttribute(tgemm_qkv, cudaFuncAttributeMaxDynamicSharedMemorySize, gsmem);
    cudaFuncSetAttribute(tgemm_wo, cudaFuncAttributeMaxDynamicSharedMemorySize, gsmem);
    cudaFuncSetAttribute(attn_mma, cudaFuncAttributeMaxDynamicSharedMemorySize, smem_attn);

    cvt_all<<<(RN4 + 255) / 256, 256>>>(x, xh, Wq, wqh, Wk, wkh, Wv, wvh, Wo, woh);

    tgemm_qkv<<<dim3(24, MTOT / 128), 128, gsmem>>>(xh, wqh, wkh, wvh, qh, kh, vh);

    attn_mma<<<dim3(NS / 128, NH, NB), 128, smem_attn>>>();

    tgemm_wo<<<dim3(ND / 64, MTOT / 128), 128, gsmem>>>(oh, woh, out);
}

// round 17
// speedup vs baseline: 1.2540x; 1.2540x over previous
#include <cuda_runtime.h>
#include <cuda_fp16.h>
#include <math.h>
#include <cstdint>

#define NB 4
#define NS 2048
#define ND 1024
#define NH 16
#define NKV 4
#define NHD 64
#define MTOT (NB * NS)   // 8192

// ---------------- scratch (static device globals; no allocation) -------------
__device__ __half g_xh[(size_t)MTOT * ND];
__device__ __half g_qh[(size_t)MTOT * ND];
__device__ __half g_kh[(size_t)MTOT * 256];
__device__ __half g_vh[(size_t)MTOT * 256];
__device__ __half g_oh[(size_t)MTOT * ND];
__device__ __half g_wqh[(size_t)ND * ND];
__device__ __half g_wkh[(size_t)ND * 256];
__device__ __half g_wvh[(size_t)ND * 256];
__device__ __half g_woh[(size_t)ND * ND];

// ---------------- helpers -----------------------------------------------------
__device__ __forceinline__ float ex2(float x) {
    float y;
    asm("ex2.approx.f32 %0, %1;" : "=f"(y) : "f"(x));
    return y;
}
__device__ __forceinline__ uint32_t h2ex2(uint32_t x) {
    uint32_t y;
    asm("ex2.approx.f16x2 %0, %1;" : "=r"(y) : "r"(x));
    return y;
}
__device__ __forceinline__ uint32_t smem_u32(const void* p) {
    uint32_t a;
    asm("{ .reg .u64 t; cvta.to.shared.u64 t, %1; cvt.u32.u64 %0, t; }" : "=r"(a) : "l"(p));
    return a;
}
__device__ __forceinline__ uint32_t packh2(float lo, float hi) {
    __half2 h = __floats2half2_rn(lo, hi);
    return *reinterpret_cast<uint32_t*>(&h);
}
__device__ __forceinline__ void ldmx4(uint32_t* r, uint32_t addr) {
    asm volatile("ldmatrix.sync.aligned.m8n8.x4.shared.b16 {%0,%1,%2,%3}, [%4];"
                 : "=r"(r[0]), "=r"(r[1]), "=r"(r[2]), "=r"(r[3]) : "r"(addr));
}
__device__ __forceinline__ void ldmx4t(uint32_t* r, uint32_t addr) {
    asm volatile("ldmatrix.sync.aligned.m8n8.x4.trans.shared.b16 {%0,%1,%2,%3}, [%4];"
                 : "=r"(r[0]), "=r"(r[1]), "=r"(r[2]), "=r"(r[3]) : "r"(addr));
}
__device__ __forceinline__ void cpa16(uint32_t dst, const void* src) {
    asm volatile("cp.async.ca.shared.global [%0], [%1], 16;" :: "r"(dst), "l"(src));
}
__device__ __forceinline__ void cpa_commit() {
    asm volatile("cp.async.commit_group;" ::: "memory");
}
__device__ __forceinline__ void cpa_wait0() {
    asm volatile("cp.async.wait_group 0;" ::: "memory");
}
__device__ __forceinline__ void cpa_wait1() {
    asm volatile("cp.async.wait_group 1;" ::: "memory");
}
__device__ __forceinline__ void mma16(float* c, const uint32_t* a, uint32_t b0, uint32_t b1) {
    asm volatile(
        "mma.sync.aligned.m16n8k16.row.col.f32.f16.f16.f32 "
        "{%0,%1,%2,%3}, {%4,%5,%6,%7}, {%8,%9}, {%0,%1,%2,%3};"
        : "+f"(c[0]), "+f"(c[1]), "+f"(c[2]), "+f"(c[3])
        : "r"(a[0]), "r"(a[1]), "r"(a[2]), "r"(a[3]), "r"(b0), "r"(b1));
}

// ---------------- merged fp32->fp16 convert kernel ---------------------------
#define RN0 (MTOT * ND / 4)
#define RN1 (RN0 + ND * ND / 4)
#define RN2 (RN1 + ND * 256 / 4)
#define RN3 (RN2 + ND * 256 / 4)
#define RN4 (RN3 + ND * ND / 4)

__global__ __launch_bounds__(256) void cvt_all(
    const float* __restrict__ x,  __half* __restrict__ xh,
    const float* __restrict__ wq, __half* __restrict__ wqh,
    const float* __restrict__ wk, __half* __restrict__ wkh,
    const float* __restrict__ wv, __half* __restrict__ wvh,
    const float* __restrict__ wo, __half* __restrict__ woh) {
    int i = blockIdx.x * 256 + threadIdx.x;
    const float* s; __half* d; int j;
    if (i < RN0)      { s = x;  d = xh;  j = i; }
    else if (i < RN1) { s = wq; d = wqh; j = i - RN0; }
    else if (i < RN2) { s = wk; d = wkh; j = i - RN1; }
    else if (i < RN3) { s = wv; d = wvh; j = i - RN2; }
    else if (i < RN4) { s = wo; d = woh; j = i - RN3; }
    else return;
    float4 v = ((const float4*)s)[j];
    ((uint2*)d)[j] = make_uint2(packh2(v.x, v.y), packh2(v.z, v.w));
}

// ---------------- fp16 GEMM: tile 128x128x32, 3-stage (R13 config) -----------
#define APH 20
#define WPH 68
#define ABUFW (128 * APH)
#define WBUFW (32 * WPH)
#define GSW (3 * (ABUFW + WBUFW))     // 14208 words = 56832 B

template <bool H16OUT>
__device__ __forceinline__ void tgemm_body(const __half* __restrict__ A,
                                           const __half* __restrict__ W,
                                           void* __restrict__ Cv,
                                           int N, int K, int bn, uint32_t* sm) {
    const int tid = threadIdx.x, wid = tid >> 5, lane = tid & 31;
    const int g = lane >> 2, tg = lane & 3;
    const int bm = blockIdx.y;
    const int wm = wid >> 1, wn = wid & 1;
    const int rowsel = lane & 15, colsel = lane >> 4;

    const uint32_t smb = smem_u32(sm);
    const uint32_t ws0 = 3 * ABUFW;

    const __half* Ap = A + (size_t)(bm * 128 + tid) * K;
    const int wrow = tid >> 4, wseg = tid & 15;
    const __half* Wp = W + (size_t)wrow * N + bn * 128 + wseg * 8;

    const int nk = K / 32;

    auto load_tile = [&](int kt, int buf) {
        const uint32_t ab = smb + (uint32_t)(buf * ABUFW) * 4;
        const uint32_t wb = smb + (uint32_t)(ws0 + buf * WBUFW) * 4;
        const __half* ap = Ap + kt * 32;
#pragma unroll
        for (int s = 0; s < 4; s++)
            cpa16(ab + (uint32_t)(tid * APH + s * 4) * 4, ap + s * 8);
        const __half* wp = Wp + (size_t)kt * 32 * N;
#pragma unroll
        for (int r = 0; r < 4; r++)
            cpa16(wb + (uint32_t)((wrow + r * 8) * WPH + wseg * 4) * 4,
                  wp + (size_t)r * 8 * N);
        cpa_commit();
    };

    float acc[4][8][4];
#pragma unroll
    for (int i = 0; i < 4; i++)
#pragma unroll
        for (int j = 0; j < 8; j++)
#pragma unroll
            for (int r = 0; r < 4; r++) acc[i][j][r] = 0.f;

    load_tile(0, 0);
    load_tile(1, 1);

    int cur = 0;
    for (int kt = 0; kt < nk; kt++) {
        if (kt + 1 < nk) cpa_wait1(); else cpa_wait0();
        __syncthreads();
        int pre = cur + 2; if (pre >= 3) pre -= 3;
        if (kt + 2 < nk) load_tile(kt + 2, pre);

        const uint32_t ab = smb + (uint32_t)(cur * ABUFW) * 4;
        const uint32_t wb = smb + (uint32_t)(ws0 + cur * WBUFW) * 4;
#pragma unroll
        for (int ks = 0; ks < 2; ks++) {
            uint32_t a[4][4];
#pragma unroll
            for (int mt = 0; mt < 4; mt++)
                ldmx4(a[mt], ab + (uint32_t)((wm * 64 + mt * 16 + rowsel) * APH +
                                             ks * 8 + colsel * 4) * 4);
#pragma unroll
            for (int np = 0; np < 4; np++) {
                uint32_t r4[4];
                ldmx4t(r4, wb + (uint32_t)((ks * 16 + rowsel) * WPH +
                                           wn * 32 + np * 8 + colsel * 4) * 4);
#pragma unroll
                for (int mt = 0; mt < 4; mt++) {
                    mma16(acc[mt][2 * np],     a[mt], r4[0], r4[1]);
                    mma16(acc[mt][2 * np + 1], a[mt], r4[2], r4[3]);
                }
            }
        }
        if (++cur == 3) cur = 0;
    }

#pragma unroll
    for (int mt = 0; mt < 4; mt++)
#pragma unroll
        for (int nt = 0; nt < 8; nt++) {
            int row = bm * 128 + wm * 64 + mt * 16 + g;
            int col = bn * 128 + wn * 64 + nt * 8 + 2 * tg;
            if (H16OUT) {
                uint32_t* C = (uint32_t*)Cv;
                C[((size_t)row * N + col) >> 1] = packh2(acc[mt][nt][0], acc[mt][nt][1]);
                C[((size_t)(row + 8) * N + col) >> 1] = packh2(acc[mt][nt][2], acc[mt][nt][3]);
            } else {
                float* C = (float*)Cv;
                *(float2*)(C + (size_t)row * N + col) =
                    make_float2(acc[mt][nt][0], acc[mt][nt][1]);
                *(float2*)(C + (size_t)(row + 8) * N + col) =
                    make_float2(acc[mt][nt][2], acc[mt][nt][3]);
            }
        }
}

// merged QKV projection: grid (12, 64). tiles 0-7 -> Q, 8-9 -> K, 10-11 -> V.
__global__ void __launch_bounds__(128, 3) tgemm_qkv(const __half* __restrict__ A,
                                                    const __half* __restrict__ wq,
                                                    const __half* __restrict__ wk,
                                                    const __half* __restrict__ wv,
                                                    __half* __restrict__ q,
                                                    __half* __restrict__ k,
                                                    __half* __restrict__ v) {
    extern __shared__ uint32_t smg[];
    const int bx = blockIdx.x;
    const __half* W; __half* C; int N, bn;
    if (bx < 8)       { W = wq; C = q; N = ND;  bn = bx; }
    else if (bx < 10) { W = wk; C = k; N = 256; bn = bx - 8; }
    else              { W = wv; C = v; N = 256; bn = bx - 10; }
    tgemm_body<true>(A, W, C, N, ND, bn, smg);
}

__global__ void __launch_bounds__(128, 3) tgemm_wo(const __half* __restrict__ A,
                                                   const __half* __restrict__ W,
                                                   float* __restrict__ C) {
    extern __shared__ uint32_t smg[];
    tgemm_body<false>(A, W, C, ND, ND, blockIdx.x, smg);
}

// ---------------- Flash attention: 3-stage K/V pipeline, ALiBi skip ----------
// e = s*sc2 + slope2*(j-(S-1)) is row-independent (softmax shift-invariance).
// Chunks with slope2*(S-1-j) > 24 are numerically irrelevant -> skip.
// exp via ex2.f16x2; row sums in fp32 via H2F unpack.
#define HP 36
#define SM_Q 0
#define KBUF (64 * HP)                  // 2304 words
#define SM_K (128 * HP)                 // 4608
#define SM_V (SM_K + 3 * KBUF)          // 11520
#define SM_TOT (SM_V + 3 * KBUF)        // 18432 words = 73728 B

__global__ void __launch_bounds__(128, 2) attn_mma() {
    extern __shared__ uint32_t sm4[];
    const uint32_t smb = smem_u32(sm4);

    const int qb = blockIdx.x, b = blockIdx.z;
    const int h = (NH - 1) - blockIdx.y;    // heavy heads first
    const int kvh = h >> 2;
    const int tid = threadIdx.x, w = tid >> 5, lane = tid & 31;
    const int g = lane >> 2, tg = lane & 3;
    const int rowsel = lane & 15, colsel = lane >> 4;

    const float LOG2E = 1.4426950408889634f;
    const float sc2 = 0.125f * LOG2E;
    const float slope2 = ex2(-0.5f * (float)(h + 1)) * LOG2E;

    const int lr = tid >> 3;
    const int lseg = tid & 7;

    const int NCH = NS / 64;
    int nneed = (int)ceilf(24.f / (64.f * slope2));
    if (nneed > NCH) nneed = NCH;
    const int kt0 = NCH - nneed;

    const __half* kbase = g_kh + (size_t)(b * NS) * 256 + kvh * NHD;
    const __half* vbase = g_vh + (size_t)(b * NS) * 256 + kvh * NHD;

    auto issue_kv = [&](int kt, int buf) {
        const __half* kp = kbase + (size_t)kt * 64 * 256;
        const __half* vp = vbase + (size_t)kt * 64 * 256;
        const uint32_t kd = smb + (uint32_t)(SM_K + buf * KBUF) * 4;
        const uint32_t vd = smb + (uint32_t)(SM_V + buf * KBUF) * 4;
#pragma unroll
        for (int rep = 0; rep < 4; rep++) {
            int r = rep * 16 + lr;
            cpa16(kd + (uint32_t)(r * HP + lseg * 4) * 4, kp + (size_t)r * 256 + lseg * 8);
            cpa16(vd + (uint32_t)(r * HP + lseg * 4) * 4, vp + (size_t)r * 256 + lseg * 8);
        }
        cpa_commit();
    };

    // prologue: kv(kt0) | Q | kv(kt0+1)   (3 commit groups)
    issue_kv(kt0, 0);
    {
        const __half* qbase = g_qh + (size_t)(b * NS + qb * 128) * ND + h * NHD;
#pragma unroll
        for (int rep = 0; rep < 8; rep++) {
            int r = rep * 16 + lr;
            cpa16(smb + (uint32_t)(SM_Q + r * HP + lseg * 4) * 4,
                  qbase + (size_t)r * ND + lseg * 8);
        }
        cpa_commit();
    }
    if (kt0 + 1 < NCH) issue_kv(kt0 + 1, 1);

    // wait so that kv(kt0) and Q are complete
    if (kt0 + 1 < NCH) cpa_wait1(); else cpa_wait0();
    __syncthreads();

    uint32_t qf[4][2][4];
#pragma unroll
    for (int ks = 0; ks < 4; ks++)
#pragma unroll
        for (int mt = 0; mt < 2; mt++)
            ldmx4(qf[ks][mt], smb + (uint32_t)(SM_Q +
                    (w * 32 + mt * 16 + rowsel) * HP + ks * 8 + colsel * 4) * 4);

    float l[4], O[2][8][4];
#pragma unroll
    for (int i = 0; i < 4; i++) l[i] = 0.f;
#pragma unroll
    for (int mt = 0; mt < 2; mt++)
#pragma unroll
        for (int nt = 0; nt < 8; nt++)
#pragma unroll
            for (int r = 0; r < 4; r++) O[mt][nt][r] = 0.f;

    int cur = 0;
    for (int kt = kt0; kt < NCH; kt++) {
        if (kt > kt0) {  // make kv(kt) visible (kt0 handled in prologue)
            if (kt + 1 < NCH) cpa_wait1(); else cpa_wait0();
            __syncthreads();
        }
        int pre = cur + 2; if (pre >= 3) pre -= 3;
        if (kt + 2 < NCH) issue_kv(kt + 2, pre);

        const uint32_t kcur = smb + (uint32_t)(SM_K + cur * KBUF) * 4;
        const uint32_t vcur = smb + (uint32_t)(SM_V + cur * KBUF) * 4;

        // S = Q K^T
        float S[2][8][4];
#pragma unroll
        for (int mt = 0; mt < 2; mt++)
#pragma unroll
            for (int nt = 0; nt < 8; nt++)
#pragma unroll
                for (int r = 0; r < 4; r++) S[mt][nt][r] = 0.f;

#pragma unroll
        for (int ks = 0; ks < 4; ks++) {
#pragma unroll
            for (int np = 0; np < 4; np++) {
                uint32_t r4[4];
                ldmx4(r4, kcur + (uint32_t)((np * 16 + rowsel) * HP +
                                            ks * 8 + colsel * 4) * 4);
                mma16(S[0][2 * np],     qf[ks][0], r4[0], r4[2]);
                mma16(S[0][2 * np + 1], qf[ks][0], r4[1], r4[3]);
                mma16(S[1][2 * np],     qf[ks][1], r4[0], r4[2]);
                mma16(S[1][2 * np + 1], qf[ks][1], r4[1], r4[3]);
            }
        }

        // static-max softmax: e fp32, pack pairs, ex2.f16x2 -> P fragments
        const float base = slope2 * (float)(kt * 64 + 2 * tg - (NS - 1));
        uint32_t ph[2][4][4];
#pragma unroll
        for (int mt = 0; mt < 2; mt++) {
#pragma unroll
            for (int nt = 0; nt < 8; nt++) {
                const float b0 = fmaf((float)(8 * nt), slope2, base);
                const float b1 = b0 + slope2;
                S[mt][nt][0] = fmaf(S[mt][nt][0], sc2, b0);
                S[mt][nt][1] = fmaf(S[mt][nt][1], sc2, b1);
                S[mt][nt][2] = fmaf(S[mt][nt][2], sc2, b0);
                S[mt][nt][3] = fmaf(S[mt][nt][3], sc2, b1);
            }
#pragma unroll
            for (int ks = 0; ks < 4; ks++) {
                ph[mt][ks][0] = h2ex2(packh2(S[mt][2 * ks][0], S[mt][2 * ks][1]));
                ph[mt][ks][1] = h2ex2(packh2(S[mt][2 * ks][2], S[mt][2 * ks][3]));
                ph[mt][ks][2] = h2ex2(packh2(S[mt][2 * ks + 1][0], S[mt][2 * ks + 1][1]));
                ph[mt][ks][3] = h2ex2(packh2(S[mt][2 * ks + 1][2], S[mt][2 * ks + 1][3]));
            }
            float rs0 = 0.f, rs1 = 0.f;
#pragma unroll
            for (int ks = 0; ks < 4; ks++) {
                float2 a0 = __half22float2(*(__half2*)&ph[mt][ks][0]);
                float2 a2 = __half22float2(*(__half2*)&ph[mt][ks][2]);
                rs0 += (a0.x + a0.y) + (a2.x + a2.y);
                float2 a1 = __half22float2(*(__half2*)&ph[mt][ks][1]);
                float2 a3 = __half22float2(*(__half2*)&ph[mt][ks][3]);
                rs1 += (a1.x + a1.y) + (a3.x + a3.y);
            }
            rs0 += __shfl_xor_sync(0xffffffffu, rs0, 1);
            rs0 += __shfl_xor_sync(0xffffffffu, rs0, 2);
            rs1 += __shfl_xor_sync(0xffffffffu, rs1, 1);
            rs1 += __shfl_xor_sync(0xffffffffu, rs1, 2);
            l[2 * mt] += rs0;
            l[2 * mt + 1] += rs1;
        }

        // O += P @ V
#pragma unroll
        for (int ks = 0; ks < 4; ks++) {
#pragma unroll
            for (int np = 0; np < 4; np++) {
                uint32_t r4[4];
                ldmx4t(r4, vcur + (uint32_t)((ks * 16 + rowsel) * HP +
                                             np * 8 + colsel * 4) * 4);
                mma16(O[0][2 * np],     ph[0][ks], r4[0], r4[1]);
                mma16(O[0][2 * np + 1], ph[0][ks], r4[2], r4[3]);
                mma16(O[1][2 * np],     ph[1][ks], r4[0], r4[1]);
                mma16(O[1][2 * np + 1], ph[1][ks], r4[2], r4[3]);
            }
        }

        if (++cur == 3) cur = 0;
    }

    // epilogue: normalize, pack fp16, store
#pragma unroll
    for (int mt = 0; mt < 2; mt++) {
        float inv0 = 1.f / l[2 * mt], inv1 = 1.f / l[2 * mt + 1];
        int rL = b * NS + qb * 128 + w * 32 + mt * 16 + g;
        uint32_t* ob = (uint32_t*)g_oh;
#pragma unroll
        for (int nt = 0; nt < 8; nt++) {
            int col = h * NHD + nt * 8 + 2 * tg;
            ob[((size_t)rL * ND + col) >> 1] =
                packh2(O[mt][nt][0] * inv0, O[mt][nt][1] * inv0);
            ob[((size_t)(rL + 8) * ND + col) >> 1] =
                packh2(O[mt][nt][2] * inv1, O[mt][nt][3] * inv1);
        }
    }
}

// ---------------- launch ------------------------------------------------------
extern "C" void kernel_launch(void* const* d_in, const int* in_sizes, int n_in,
                              void* d_out, int out_size) {
    const float* x  = (const float*)d_in[0];
    const float* Wq = (const float*)d_in[1];
    const float* Wk = (const float*)d_in[2];
    const float* Wv = (const float*)d_in[3];
    const float* Wo = (const float*)d_in[4];
    float* out = (float*)d_out;

    __half *xh, *qh, *kh, *vh, *oh, *wqh, *wkh, *wvh, *woh;
    cudaGetSymbolAddress((void**)&xh, g_xh);
    cudaGetSymbolAddress((void**)&qh, g_qh);
    cudaGetSymbolAddress((void**)&kh, g_kh);
    cudaGetSymbolAddress((void**)&vh, g_vh);
    cudaGetSymbolAddress((void**)&oh, g_oh);
    cudaGetSymbolAddress((void**)&wqh, g_wqh);
    cudaGetSymbolAddress((void**)&wkh, g_wkh);
    cudaGetSymbolAddress((void**)&wvh, g_wvh);
    cudaGetSymbolAddress((void**)&woh, g_woh);

    const int gsmem = GSW * sizeof(uint32_t);          // 56832 B
    const int smem_attn = SM_TOT * sizeof(uint32_t);   // 73728 B
    cudaFuncSetAttribute(tgemm_qkv, cudaFuncAttributeMaxDynamicSharedMemorySize, gsmem);
    cudaFuncSetAttribute(tgemm_wo, cudaFuncAttributeMaxDynamicSharedMemorySize, gsmem);
    cudaFuncSetAttribute(attn_mma, cudaFuncAttributeMaxDynamicSharedMemorySize, smem_attn);

    cvt_all<<<(RN4 + 255) / 256, 256>>>(x, xh, Wq, wqh, Wk, wkh, Wv, wvh, Wo, woh);

    tgemm_qkv<<<dim3(12, MTOT / 128), 128, gsmem>>>(xh, wqh, wkh, wvh, qh, kh, vh);

    attn_mma<<<dim3(NS / 128, NH, NB), 128, smem_attn>>>();

    tgemm_wo<<<dim3(ND / 128, MTOT / 128), 128, gsmem>>>(oh, woh, out);
}